// round 15
// baseline (speedup 1.0000x reference)
#include <cuda_runtime.h>

#define Bn 16
#define Hn 720
#define Wn 1280
#define PLANE (Hn * Wn)
#define NPIX (Bn * PLANE)
#define TPB 256
#define CHUNK 5            // Wn / TPB
#define BIGI (1 << 30)

#define XT 8               // columns per k_col block
#define SEG 120            // segments per column
#define RSEG 6             // rows per segment (SEG*RSEG == Hn)

// Splat accumulator: x=sum(-fx), y=sum(-fy), z=count, w=pad.
// Zero-initialized at module load; k_col restores zeros every call so the
// all-zero invariant holds on entry to every kernel_launch / graph replay.
__device__ float4 g_splat[NPIX];
// Compressed planar partials after row pass:
//   valid pixel: pXY = final out values, pNH = -1
//   hole pixel : pXY = left/right sums,  pNH = left/right count (0..2)
__device__ float2 g_pXY[NPIX];
__device__ signed char g_pNH[NPIX];

// ---------------------------------------------------------------- scatter
// One RED.128 per valid source pixel (4 corners = 2x2 box-sum in k_row).
__global__ void k_scatter(const float* __restrict__ in) {
    int p = blockIdx.x * blockDim.x + threadIdx.x;
    if (p >= PLANE) return;
    int b = blockIdx.y;
    int y = p / Wn;
    int x = p - y * Wn;

    float fx = in[(size_t)(2 * b    ) * PLANE + p];
    float fy = in[(size_t)(2 * b + 1) * PLANE + p];

    float x2 = (float)x + fx;
    float y2 = (float)y + fy;
    if (!(x2 >= 0.f && y2 >= 0.f && x2 <= (float)(Wn - 1) && y2 <= (float)(Hn - 1)))
        return;

    int xL = (int)floorf(x2); xL = max(0, min(xL, Wn - 1));
    int yT = (int)floorf(y2); yT = max(0, min(yT, Hn - 1));

    float4* dst = &g_splat[(size_t)b * PLANE + yT * Wn + xL];
    atomicAdd(dst, make_float4(-fx, -fy, 1.f, 0.f));

    // Degenerate clamp: corners coincide when x2/y2 hit the exact border.
    // True multiplicity at the single corner is (1+ex)*(1+ey); the box-sum
    // delivers it once, so add the missing (mult-1)*v.
    int ex = (x2 == (float)(Wn - 1));
    int ey = (y2 == (float)(Hn - 1));
    int m = (1 + ex) * (1 + ey) - 1;
    if (m) atomicAdd(dst, make_float4(-fx * m, -fy * m, (float)m, 0.f));
}

// ------------------------------------- box-sum + normalize + row fill
// Two output rows per block; splat rows y0-1,y0,y0+1 are read directly from
// global into registers (1-element halo per thread), ONE __syncthreads.
__global__ __launch_bounds__(TPB) void k_row(float* __restrict__ outp) {
    __shared__ float sX[2][Wn], sY[2][Wn];   // normalized values per row
    __shared__ int wLs[2][8], wRs[2][8];

    int g = blockIdx.x;                // g = b*(Hn/2) + (y0/2)
    int b = g / (Hn / 2);
    int y0 = (g - b * (Hn / 2)) * 2;   // first of the two output rows
    size_t bbase = (size_t)b * PLANE;
    int tid = threadIdx.x;
    int lane = tid & 31;
    int wid = tid >> 5;
    int x0 = tid * CHUNK;

    // Load 6 float4 per row (positions x0-1 .. x0+4) from splat rows
    // y0-1, y0, y0+1; fold vertically into the two per-output-row sums.
    float vX[2][CHUNK + 1], vY[2][CHUNK + 1], vC[2][CHUNK + 1];
    {
        size_t r0 = bbase + (size_t)y0 * Wn;        // row y0
        size_t rp = r0 + Wn;                        // row y0+1 (always < Hn)
        size_t rmv = r0 - Wn;                       // row y0-1 (guard y0==0)
        bool hasm = (y0 > 0);
        #pragma unroll
        for (int i = 0; i <= CHUNK; i++) {
            int xx = x0 - 1 + i;
            float4 a0, am, ap;
            if (xx >= 0) {
                a0 = g_splat[r0 + xx];
                ap = g_splat[rp + xx];
                am = hasm ? g_splat[rmv + xx] : make_float4(0.f, 0.f, 0.f, 0.f);
            } else {
                a0 = make_float4(0.f, 0.f, 0.f, 0.f);
                ap = a0; am = a0;
            }
            vX[0][i] = am.x + a0.x; vY[0][i] = am.y + a0.y; vC[0][i] = am.z + a0.z;
            vX[1][i] = a0.x + ap.x; vY[1][i] = a0.y + ap.y; vC[1][i] = a0.z + ap.z;
        }
    }

    // Horizontal box fold + normalize + local scans, both rows.
    int lloc[2][CHUNK], rloc[2][CHUNK];
    int linc[2], rinc[2];
    #pragma unroll
    for (int j = 0; j < 2; j++) {
        int lm = -1;
        #pragma unroll
        for (int k = 0; k < CHUNK; k++) {
            int xx = x0 + k;
            float ax = vX[j][k + 1] + vX[j][k];
            float ay = vY[j][k + 1] + vY[j][k];
            float ac = vC[j][k + 1] + vC[j][k];
            bool h = (ac > 0.f);
            float inv = h ? (1.f / ac) : 0.f;
            sX[j][xx] = ax * inv;
            sY[j][xx] = ay * inv;
            if (h) lm = xx;
            lloc[j][k] = lm;
        }
        int rm = BIGI;
        #pragma unroll
        for (int k = CHUNK - 1; k >= 0; k--) {
            int xx = x0 + k;
            if (lloc[j][k] == xx) rm = xx;   // valid at xx
            rloc[j][k] = rm;
        }
        // warp shuffle scans (inclusive)
        int li = lm;
        #pragma unroll
        for (int off = 1; off < 32; off <<= 1) {
            int v = __shfl_up_sync(0xffffffffu, li, off);
            if (lane >= off) li = max(li, v);
        }
        int ri = rm;
        #pragma unroll
        for (int off = 1; off < 32; off <<= 1) {
            int v = __shfl_down_sync(0xffffffffu, ri, off);
            if (lane + off < 32) ri = min(ri, v);
        }
        linc[j] = li; rinc[j] = ri;
        if (lane == 31) wLs[j][wid] = li;
        if (lane == 0)  wRs[j][wid] = ri;
    }
    __syncthreads();   // publishes sX/sY + warp scan results

    #pragma unroll
    for (int j = 0; j < 2; j++) {
        int y = y0 + j;
        size_t base = bbase + (size_t)y * Wn;

        int cL = -1;
        for (int w2 = 0; w2 < wid; w2++) cL = max(cL, wLs[j][w2]);
        int le = __shfl_up_sync(0xffffffffu, linc[j], 1);
        int carryL = max(cL, (lane > 0) ? le : -1);

        int cR = BIGI;
        for (int w2 = wid + 1; w2 < 8; w2++) cR = min(cR, wRs[j][w2]);
        int re = __shfl_down_sync(0xffffffffu, rinc[j], 1);
        int carryR = min(cR, (lane < 31) ? re : BIGI);

        float* outX = outp + ((size_t)(2 * b    ) * Hn + y) * Wn;
        float* outY = outp + ((size_t)(2 * b + 1) * Hn + y) * Wn;

        #pragma unroll
        for (int k = 0; k < CHUNK; k++) {
            int xx = x0 + k;
            int L = max(carryL, lloc[j][k]);
            int R = min(carryR, rloc[j][k]);
            if (L == xx) {     // valid pixel
                float ox = sX[j][xx], oy = sY[j][xx];
                outX[xx] = ox;
                outY[xx] = oy;
                g_pXY[base + xx] = make_float2(ox, oy);
                g_pNH[base + xx] = (signed char)(-1);
            } else {           // hole: left/right partial
                float sx = 0.f, sy = 0.f;
                int num = 0;
                if (L >= 0) { sx += sX[j][L]; sy += sY[j][L]; num++; }
                if (R < Wn) { sx += sX[j][R]; sy += sY[j][R]; num++; }
                g_pXY[base + xx] = make_float2(sx, sy);
                g_pNH[base + xx] = (signed char)num;
            }
        }
    }
}

// ------------------------------------------- parallel column fill
// block = (XT columns, SEG segments); each thread holds RSEG rows in regs.
// Also restores the splat accumulator to zero for the next graph replay
// (k_col is latency-bound with bandwidth slack: measured ~free).
__global__ __launch_bounds__(XT * SEG, 1) void k_col(float* __restrict__ outp) {
    __shared__ float4 sD[SEG][XT];   // "first valid at/below" scan
    __shared__ float4 sU[SEG][XT];   // "last valid at/above" scan

    int tx = threadIdx.x;
    int ts = threadIdx.y;
    int b  = blockIdx.y;
    int gx = blockIdx.x * XT + tx;
    size_t cbase = (size_t)b * PLANE + gx;
    int y0 = ts * RSEG;

    float rx[RSEG], ry[RSEG], rn[RSEG];

    float4 dsum = make_float4(0.f, 0.f, 0.f, 0.f);   // topmost valid in seg
    float4 usum = make_float4(0.f, 0.f, 0.f, 0.f);   // bottom-most valid in seg
    #pragma unroll
    for (int k = 0; k < RSEG; k++) {
        size_t idx = cbase + (size_t)(y0 + k) * Wn;
        float2 pv = g_pXY[idx];
        signed char nh = g_pNH[idx];
        rx[k] = pv.x; ry[k] = pv.y;
        if (nh < 0) {
            rn[k] = -1.f;
            if (dsum.z == 0.f) dsum = make_float4(pv.x, pv.y, 1.f, 0.f);
            usum = make_float4(pv.x, pv.y, 1.f, 0.f);
        } else {
            rn[k] = (float)nh;
        }
    }
    sD[ts][tx] = dsum;
    sU[ts][tx] = usum;

    // restore splat accumulator to zero (invariant for next kernel_launch)
    #pragma unroll
    for (int k = 0; k < RSEG; k++)
        g_splat[cbase + (size_t)(y0 + k) * Wn] = make_float4(0.f, 0.f, 0.f, 0.f);
    __syncthreads();

    // Hillis-Steele "nearest valid" scans along segments (both directions)
    for (int off = 1; off < SEG; off <<= 1) {
        float4 myD = sD[ts][tx];
        float4 myU = sU[ts][tx];
        float4 dv = (ts + off < SEG) ? sD[ts + off][tx] : make_float4(0.f, 0.f, 0.f, 0.f);
        float4 uv = (ts >= off)      ? sU[ts - off][tx] : make_float4(0.f, 0.f, 0.f, 0.f);
        __syncthreads();
        if (myD.z == 0.f) sD[ts][tx] = dv;
        if (myU.z == 0.f) sU[ts][tx] = uv;
        __syncthreads();
    }

    float4 cd = (ts + 1 < SEG) ? sD[ts + 1][tx] : make_float4(0.f, 0.f, 0.f, 0.f);
    float4 cu = (ts > 0)       ? sU[ts - 1][tx] : make_float4(0.f, 0.f, 0.f, 0.f);

    // down apply (bottom-up)
    #pragma unroll
    for (int k = RSEG - 1; k >= 0; k--) {
        if (rn[k] < 0.f) {
            cd = make_float4(rx[k], ry[k], 1.f, 0.f);
        } else {
            rx[k] += cd.x; ry[k] += cd.y; rn[k] += cd.z;
        }
    }

    // up apply (top-down) + finalize hole outputs
    float* oX = outp + (size_t)(2 * b    ) * PLANE + gx;
    float* oY = outp + (size_t)(2 * b + 1) * PLANE + gx;
    #pragma unroll
    for (int k = 0; k < RSEG; k++) {
        if (rn[k] < 0.f) {
            cu = make_float4(rx[k], ry[k], 1.f, 0.f);
        } else {
            float sx  = rx[k] + cu.x;
            float sy  = ry[k] + cu.y;
            float num = rn[k] + cu.z;
            float ox = 0.f, oy = 0.f;
            if (num > 0.f) {
                float inv = 1.f / num;
                ox = sx * inv;
                oy = sy * inv;
            }
            size_t off = (size_t)(y0 + k) * Wn;
            oX[off] = ox;
            oY[off] = oy;
        }
    }
}

// ---------------------------------------------------------------- launch
extern "C" void kernel_launch(void* const* d_in, const int* in_sizes, int n_in,
                              void* d_out, int out_size) {
    const float* in = (const float*)d_in[0];
    float* out = (float*)d_out;

    dim3 gs((PLANE + 255) / 256, Bn);
    k_scatter<<<gs, 256>>>(in);

    k_row<<<Bn * (Hn / 2), TPB>>>(out);

    dim3 gc(Wn / XT, Bn);
    dim3 bc(XT, SEG);
    k_col<<<gc, bc>>>(out);
}